// round 15
// baseline (speedup 1.0000x reference)
#include <cuda_runtime.h>
#include <cuda_fp16.h>
#include <cstdint>

#define B_   8
#define CIN  64
#define COUT 128
#define L_   18
#define LV   16
#define H_   32
#define W_   32
#define HW   1024
#define NH   2
#define DQ   9
#define DV   8
#define KSPL 2            // logit K split

// Scratch (static device globals; no runtime allocation allowed)
__device__ uint32_t g_ini [B_*CIN*L_*HW];            // input  (hi,lo) interleaved
__device__ uint32_t g_memi[B_*CIN*L_*HW];            // memory (hi,lo) interleaved
__device__ uint32_t g_wqi[COUT*CIN*9];               // weights, tap-major, interleaved
__device__ uint32_t g_wki[COUT*CIN*9];
__device__ uint32_t g_wvi[COUT*CIN*27];
__device__ __half g_qh[B_*COUT*L_*HW];               // q hi halves
__device__ __half g_ql[B_*COUT*L_*HW];               // q lo halves
__device__ __half g_kh[B_*COUT*L_*HW];
__device__ __half g_kl[B_*COUT*L_*HW];
__device__ float  g_v[B_*COUT*LV*HW];                // 67 MB
__device__ float  g_lp[KSPL*B_*NH*DQ*COUT*COUT];     // 18.9 MB
__device__ float  g_attn[B_*NH*COUT*COUT];           // 1 MB

typedef unsigned long long ull;

// ---------------------------------------------------------------------------
// fp16 helpers
// ---------------------------------------------------------------------------
__device__ __forceinline__ uint32_t f2h2(float x0, float x1) {
    uint32_t r;
    asm("cvt.rn.f16x2.f32 %0, %1, %2;" : "=r"(r) : "f"(x1), "f"(x0));
    return r;   // lo half = x0, hi half = x1 (memory order)
}
__device__ __forceinline__ float2 h2f2(uint32_t u) {
    __half2 h = *(__half2*)&u;
    return __half22float2(h);
}
__device__ __forceinline__ uint32_t ileave(float x) {
    __half h = __float2half_rn(x);
    float hf = __half2float(h);
    __half l = __float2half_rn(x - hf);
    return (uint32_t)__half_as_ushort(h) | ((uint32_t)__half_as_ushort(l) << 16);
}

// mma.sync m16n8k16 fp16 (baseline PTX, works on plain sm_103)
__device__ __forceinline__ void mma_f16(float* d, const uint32_t* a,
                                        uint32_t b0, uint32_t b1) {
    asm volatile(
        "mma.sync.aligned.m16n8k16.row.col.f32.f16.f16.f32 "
        "{%0,%1,%2,%3}, {%4,%5,%6,%7}, {%8,%9}, {%0,%1,%2,%3};"
        : "+f"(d[0]), "+f"(d[1]), "+f"(d[2]), "+f"(d[3])
        : "r"(a[0]), "r"(a[1]), "r"(a[2]), "r"(a[3]), "r"(b0), "r"(b1));
}

// f32x2 helpers (out_kernel)
__device__ __forceinline__ ull pack2(float x, float y) {
    ull r; asm("mov.b64 %0, {%1, %2};" : "=l"(r) : "f"(x), "f"(y)); return r;
}
__device__ __forceinline__ float2 unpack2(ull v) {
    float2 r; asm("mov.b64 {%0, %1}, %2;" : "=f"(r.x), "=f"(r.y) : "l"(v)); return r;
}
__device__ __forceinline__ void ffma2(ull& d, ull a, ull b) {
    asm("fma.rn.f32x2 %0, %1, %2, %0;" : "+l"(d) : "l"(a), "l"(b));
}

#define KC   32          // K elems per chunk
#define SW   20          // A / logit smem row stride (u32 words)
#define SWB  136         // conv B smem k-pair-row stride (u32 words)

// ---------------------------------------------------------------------------
// Prepass: elementwise (hi,lo) interleave of an f32 array (vectorized x4)
// ---------------------------------------------------------------------------
__global__ __launch_bounds__(256) void interleave_kernel(
    const float4* __restrict__ src, uint4* __restrict__ dst, int n4)
{
    int i = blockIdx.x * 256 + threadIdx.x;
    if (i < n4) {
        float4 v = src[i];
        dst[i] = make_uint4(ileave(v.x), ileave(v.y), ileave(v.z), ileave(v.w));
    }
}

// Prepass: weight reorder (ci,tap)->(tap,ci) + interleave. grid COUT.
__global__ __launch_bounds__(256) void wreorder_kernel(
    const float* __restrict__ src, uint32_t* __restrict__ dst, int taps)
{
    int co = blockIdx.x;
    int K = 64 * taps;
    for (int j = threadIdx.x; j < K; j += 256) {
        int ci  = j & 63;
        int tap = j >> 6;
        dst[co * K + j] = ileave(src[co * K + ci * taps + tap]);
    }
}

// ---------------------------------------------------------------------------
// Conv MMA core: A [co][kp] stride SW, B [kp][px] stride SWB.
// NSEG=3: ah*bh + al*bh + ah*bl.  NSEG=2: ah*bh + al*bh (no Bl).
// ---------------------------------------------------------------------------
template<int NSEG>
__device__ __forceinline__ void mma_chunk_bk(
    float acc[2][8][4],
    const uint32_t* Ah, const uint32_t* Al,
    const uint32_t* Bh, const uint32_t* Bl,
    int wm, int wn, int lid)
{
    const int qr = lid >> 2;
    const int qc = lid & 3;
#pragma unroll
    for (int ks = 0; ks < 2; ks++) {
        const int base = ks << 3;
        uint32_t ah[2][4], al[2][4];
#pragma unroll
        for (int mt = 0; mt < 2; mt++) {
            int r0 = (wm << 5) + (mt << 4) + qr;
            int w0 = r0 * SW + base + qc;
            int w1 = (r0 + 8) * SW + base + qc;
            ah[mt][0] = Ah[w0];     ah[mt][1] = Ah[w1];
            ah[mt][2] = Ah[w0 + 4]; ah[mt][3] = Ah[w1 + 4];
            al[mt][0] = Al[w0];     al[mt][1] = Al[w1];
            al[mt][2] = Al[w0 + 4]; al[mt][3] = Al[w1 + 4];
        }
        uint32_t bf[8][2];
#pragma unroll
        for (int nt = 0; nt < 8; nt++) {
            int n = (wn << 6) + (nt << 3) + qr;
            bf[nt][0] = Bh[(base + qc) * SWB + n];
            bf[nt][1] = Bh[(base + qc + 4) * SWB + n];
        }
#pragma unroll
        for (int nt = 0; nt < 8; nt++) {
            mma_f16(acc[0][nt], ah[0], bf[nt][0], bf[nt][1]);
            mma_f16(acc[1][nt], ah[1], bf[nt][0], bf[nt][1]);
        }
#pragma unroll
        for (int nt = 0; nt < 8; nt++) {
            mma_f16(acc[0][nt], al[0], bf[nt][0], bf[nt][1]);
            mma_f16(acc[1][nt], al[1], bf[nt][0], bf[nt][1]);
        }
        if (NSEG == 3) {
#pragma unroll
            for (int nt = 0; nt < 8; nt++) {
                int n = (wn << 6) + (nt << 3) + qr;
                bf[nt][0] = Bl[(base + qc) * SWB + n];
                bf[nt][1] = Bl[(base + qc + 4) * SWB + n];
            }
#pragma unroll
            for (int nt = 0; nt < 8; nt++) {
                mma_f16(acc[0][nt], ah[0], bf[nt][0], bf[nt][1]);
                mma_f16(acc[1][nt], ah[1], bf[nt][0], bf[nt][1]);
            }
        }
    }
}

// Logit variant: both A and B in [row][kp] layout, stride SW. 3 segments.
__device__ __forceinline__ void mma_chunk(
    float acc[2][8][4],
    const uint32_t* Ah, const uint32_t* Al,
    const uint32_t* Bh, const uint32_t* Bl,
    int wm, int wn, int lid)
{
    const int qr = lid >> 2;
    const int qc = lid & 3;
#pragma unroll
    for (int ks = 0; ks < 2; ks++) {
        const int base = ks << 3;
        uint32_t ah[2][4], al[2][4];
#pragma unroll
        for (int mt = 0; mt < 2; mt++) {
            int r0 = (wm << 5) + (mt << 4) + qr;
            int w0 = r0 * SW + base + qc;
            int w1 = (r0 + 8) * SW + base + qc;
            ah[mt][0] = Ah[w0];     ah[mt][1] = Ah[w1];
            ah[mt][2] = Ah[w0 + 4]; ah[mt][3] = Ah[w1 + 4];
            al[mt][0] = Al[w0];     al[mt][1] = Al[w1];
            al[mt][2] = Al[w0 + 4]; al[mt][3] = Al[w1 + 4];
        }
        uint32_t bf[8][2];
#pragma unroll
        for (int nt = 0; nt < 8; nt++) {
            int n = (wn << 6) + (nt << 3) + qr;
            int w = n * SW + base + qc;
            bf[nt][0] = Bh[w]; bf[nt][1] = Bh[w + 4];
        }
#pragma unroll
        for (int nt = 0; nt < 8; nt++) {
            mma_f16(acc[0][nt], ah[0], bf[nt][0], bf[nt][1]);
            mma_f16(acc[1][nt], ah[1], bf[nt][0], bf[nt][1]);
        }
#pragma unroll
        for (int nt = 0; nt < 8; nt++) {
            mma_f16(acc[0][nt], al[0], bf[nt][0], bf[nt][1]);
            mma_f16(acc[1][nt], al[1], bf[nt][0], bf[nt][1]);
        }
#pragma unroll
        for (int nt = 0; nt < 8; nt++) {
            int n = (wn << 6) + (nt << 3) + qr;
            int w = n * SW + base + qc;
            bf[nt][0] = Bl[w]; bf[nt][1] = Bl[w + 4];
        }
#pragma unroll
        for (int nt = 0; nt < 8; nt++) {
            mma_f16(acc[0][nt], ah[0], bf[nt][0], bf[nt][1]);
            mma_f16(acc[1][nt], ah[1], bf[nt][0], bf[nt][1]);
        }
    }
}

// ---------------------------------------------------------------------------
// Implicit-GEMM conv, pre-split inputs, tap-major K, B register prefetch.
// grid (8 hw-tiles, LOUT, B_), block 256 (8 warps, each 32co x 64hw), 2 CTA/SM.
// SPLITOUT: write (hi,lo) half arrays (q/k) instead of f32 (v).
// ---------------------------------------------------------------------------
template<int TAPS, int LOUT, int NSEG, bool SPLITOUT>
__global__ __launch_bounds__(256, 2) void conv_mma_kernel(
    const uint32_t* __restrict__ ini, const uint32_t* __restrict__ wi,
    const float* __restrict__ bias, float* __restrict__ dstf,
    __half* __restrict__ dsth, __half* __restrict__ dstl, float scale)
{
    constexpr int KSEG = 64 * TAPS;           // 576 or 1728
    constexpr int NCHUNK = KSEG / KC;         // 18 or 54
    __shared__ uint32_t Ah[128*SW], Al[128*SW];        // A: [co][kp]
    __shared__ uint32_t Bh[16*SWB], Bl[16*SWB];        // B: [kp][px]

    const int tid = threadIdx.x;
    const int wid = tid >> 5;
    const int lid = tid & 31;
    const int wm  = wid & 3;
    const int wn  = wid >> 2;
    const int l   = blockIdx.y;
    const int b   = blockIdx.z;
    const int hw0 = blockIdx.x << 7;

    const uint32_t* inb = ini + (size_t)b*CIN*L_*HW + (size_t)l*HW;

    // A-build mapping: lanes along k
    const int kp_a = tid & 15;
    const int rw_a = tid >> 4;
    // B-build mapping: lanes along pixels
    const int px   = tid & 127;
    const int kq   = tid >> 7;                // 0/1
    const int bh_  = (hw0 + px) >> 5;
    const int bw_  = px & 31;

    float acc[2][8][4];
#pragma unroll
    for (int i = 0; i < 2; i++)
#pragma unroll
        for (int j = 0; j < 8; j++)
#pragma unroll
            for (int r = 0; r < 4; r++) acc[i][j][r] = 0.f;

    uint32_t br[8][2];                        // B prefetch (raw interleaved)
    auto loadB = [&](int tb) {
#pragma unroll
        for (int it = 0; it < 8; it++) {
            int kp  = (it << 1) + kq;
            int t0  = tb + (kp << 1);         // even; tap-major: tap=t0>>6, ci=t0&63
            int tap = t0 >> 6;
            int cib = t0 & 63;
            int dl, dh, dw;
            if (TAPS == 27) { dl = tap / 9; int r = tap - dl * 9; dh = r / 3; dw = r - dh * 3; }
            else            { dl = 0; dh = tap / 3; dw = tap - dh * 3; }
            int hh = bh_ + dh - 1, ww = bw_ + dw - 1;
            bool ok = ((unsigned)hh < (unsigned)H_) && ((unsigned)ww < (unsigned)W_);
            const uint32_t* p = inb + ((size_t)cib * L_ + dl) * HW + hh * W_ + ww;
            br[it][0] = ok ? p[0] : 0u;             // element (ci, tap)
            br[it][1] = ok ? p[(size_t)L_ * HW] : 0u; // element (ci+1, tap)
        }
    };

    loadB(0);

#pragma unroll 1
    for (int c = 0; c < NCHUNK; c++) {
        const int tb = c * KC;
        // A tile: direct (weights L2-resident): LDG.64 -> 2 prmt -> 2 STS
#pragma unroll
        for (int q = 0; q < 8; q++) {
            int row = rw_a + (q << 4);
            uint2 wv = *(const uint2*)(wi + (size_t)row * KSEG + tb + (kp_a << 1));
            Ah[row*SW + kp_a] = __byte_perm(wv.x, wv.y, 0x5410);
            Al[row*SW + kp_a] = __byte_perm(wv.x, wv.y, 0x7632);
        }
        // B tile from prefetch regs
#pragma unroll
        for (int it = 0; it < 8; it++) {
            int kp = (it << 1) + kq;
            Bh[kp*SWB + px] = __byte_perm(br[it][0], br[it][1], 0x5410);
            if (NSEG == 3)
                Bl[kp*SWB + px] = __byte_perm(br[it][0], br[it][1], 0x7632);
        }
        __syncthreads();
        if (c + 1 < NCHUNK) loadB((c + 1) * KC);
        mma_chunk_bk<NSEG>(acc, Ah, Al, Bh, Bl, wm, wn, lid);
        __syncthreads();
    }

    // Epilogue
#pragma unroll
    for (int mt = 0; mt < 2; mt++) {
        int co = (wm << 5) + (mt << 4) + (lid >> 2);
        float bi0 = bias[co];
        float bi1 = bias[co + 8];
        size_t base0 = ((size_t)(b * COUT + co)     * LOUT + l) * HW + hw0;
        size_t base1 = ((size_t)(b * COUT + co + 8) * LOUT + l) * HW + hw0;
#pragma unroll
        for (int nt = 0; nt < 8; nt++) {
            int colp = (wn << 6) + (nt << 3) + ((lid & 3) << 1);
            float v0 = (acc[mt][nt][0] + bi0) * scale;
            float v1 = (acc[mt][nt][1] + bi0) * scale;
            float v2 = (acc[mt][nt][2] + bi1) * scale;
            float v3 = (acc[mt][nt][3] + bi1) * scale;
            if (SPLITOUT) {
                uint32_t hi = f2h2(v0, v1);
                float2 hf = h2f2(hi);
                uint32_t lo = f2h2(v0 - hf.x, v1 - hf.y);
                *(uint32_t*)(dsth + base0 + colp) = hi;
                *(uint32_t*)(dstl + base0 + colp) = lo;
                hi = f2h2(v2, v3);
                hf = h2f2(hi);
                lo = f2h2(v2 - hf.x, v3 - hf.y);
                *(uint32_t*)(dsth + base1 + colp) = hi;
                *(uint32_t*)(dstl + base1 + colp) = lo;
            } else {
                *(float2*)(dstf + base0 + colp) = make_float2(v0, v1);
                *(float2*)(dstf + base1 + colp) = make_float2(v2, v3);
            }
        }
    }
}

// ---------------------------------------------------------------------------
// Logit partial per (ck, b, n, d): D[c=128, m=128] over 512 pixels; q/k
// pre-split halves. grid KSPL*144, block 256, 2 CTA/SM.
// ---------------------------------------------------------------------------
__global__ __launch_bounds__(256, 2) void logit_mma_kernel(
    const __half* __restrict__ qh, const __half* __restrict__ ql,
    const __half* __restrict__ kh, const __half* __restrict__ kl,
    float* __restrict__ lp)
{
    constexpr int NCHUNK = HW / (KC * KSPL);  // 16
    __shared__ uint32_t Ah[128*SW], Al[128*SW], Bh[128*SW], Bl[128*SW];

    const int tid = threadIdx.x;
    const int wid = tid >> 5;
    const int lid = tid & 31;
    const int wm  = wid & 3;
    const int wn  = wid >> 2;
    const int ck  = blockIdx.x / (B_*NH*DQ);
    const int bnd = blockIdx.x % (B_*NH*DQ);
    const int d   = bnd % DQ;
    const int bn  = bnd / DQ;
    const int n_  = bn & 1;
    const int b   = bn >> 1;
    const int ldep = n_ * DQ + d;

    const size_t rowoff = ((size_t)b * COUT * L_ + ldep) * HW;
    const __half* qhb = qh + rowoff;
    const __half* qlb = ql + rowoff;
    const __half* khb = kh + rowoff;
    const __half* klb = kl + rowoff;

    float acc[2][8][4];
#pragma unroll
    for (int i = 0; i < 2; i++)
#pragma unroll
        for (int j = 0; j < 8; j++)
#pragma unroll
            for (int r = 0; r < 4; r++) acc[i][j][r] = 0.f;

    const int kp_b = tid & 15;
    const int rw_b = tid >> 4;
    const int base0 = ck * (HW/KSPL);

#pragma unroll 1
    for (int c = 0; c < NCHUNK; c++) {
        const int tb = base0 + c * KC;
#pragma unroll
        for (int qq = 0; qq < 8; qq++) {
            int row = rw_b + (qq << 4);
            size_t off = (size_t)row * (L_*HW) + tb + (kp_b << 1);
            Ah[row*SW + kp_b] = *(const uint32_t*)(qhb + off);
            Al[row*SW + kp_b] = *(const uint32_t*)(qlb + off);
            Bh[row*SW + kp_b] = *(const uint32_t*)(khb + off);
            Bl[row*SW + kp_b] = *(const uint32_t*)(klb + off);
        }
        __syncthreads();
        mma_chunk(acc, Ah, Al, Bh, Bl, wm, wn, lid);
        __syncthreads();
    }

    float* o = lp + (size_t)blockIdx.x * COUT * COUT;
#pragma unroll
    for (int mt = 0; mt < 2; mt++) {
        int cc = (wm << 5) + (mt << 4) + (lid >> 2);
#pragma unroll
        for (int nt = 0; nt < 8; nt++) {
            int m = (wn << 6) + (nt << 3) + ((lid & 3) << 1);
            *(float2*)(o + (size_t)cc * COUT + m) =
                make_float2(acc[mt][nt][0], acc[mt][nt][1]);
            *(float2*)(o + (size_t)(cc + 8) * COUT + m) =
                make_float2(acc[mt][nt][2], acc[mt][nt][3]);
        }
    }
}

// ---------------------------------------------------------------------------
// Sum KSPL*DQ partials + row softmax over m. One block per (bn, c).
// ---------------------------------------------------------------------------
__global__ __launch_bounds__(128) void softmax_kernel(
    const float* __restrict__ lp, float* __restrict__ attn)
{
    const int row = blockIdx.x;
    const int bn  = row >> 7;
    const int c   = row & 127;
    const int m   = threadIdx.x;

    float s = 0.f;
#pragma unroll
    for (int ch = 0; ch < KSPL; ch++)
#pragma unroll
        for (int dd = 0; dd < DQ; dd++)
            s += lp[(((size_t)(ch*(B_*NH*DQ) + bn*DQ + dd))*COUT + c)*COUT + m];

    __shared__ float red[128];
    red[m] = s;
    __syncthreads();
    for (int off = 64; off > 0; off >>= 1) {
        if (m < off) red[m] = fmaxf(red[m], red[m + off]);
        __syncthreads();
    }
    float mx = red[0];
    __syncthreads();
    float e = expf(s - mx);
    red[m] = e;
    __syncthreads();
    for (int off = 64; off > 0; off >>= 1) {
        if (m < off) red[m] = red[m] + red[m + off];
        __syncthreads();
    }
    attn[row*COUT + m] = e / red[0];
}

// ---------------------------------------------------------------------------
// out[b,c,n*8+d,hw] = sum_m attn[bn,c,m] * v[b,m,n*8+d,hw]  (f32x2 scalar)
// ---------------------------------------------------------------------------
__global__ __launch_bounds__(256) void out_kernel(
    const float* __restrict__ attn, const float* __restrict__ v, float* __restrict__ out)
{
    const int tile = blockIdx.x;
    const int bn   = blockIdx.y;
    const int b    = bn >> 1;
    const int n    = bn & 1;
    const int d    = (tile << 6) >> 10;
    const int hw0  = (tile << 6) & 1023;
    const int tid  = threadIdx.x;
    const int px   = tid & 63;
    const int cg   = tid >> 6;
    const int c0   = cg << 5;
    const int hw   = hw0 + px;

    __shared__ float As2[64*132];
    const float* ab = attn + bn*COUT*COUT;
    const float* vb = v + ((size_t)b*COUT*LV + n*DV + d)*HW + hw;

    ull acc2[16];
#pragma unroll
    for (int j = 0; j < 16; j++) acc2[j] = 0ull;

    for (int mc = 0; mc < 2; mc++) {
        __syncthreads();
        for (int i = tid; i < 64*128; i += 256) {
            int ml = i & 63;
            int c  = i >> 6;
            As2[ml*132 + c] = ab[c*COUT + (mc << 6) + ml];
        }
        __syncthreads();
#pragma unroll 4
        for (int ml = 0; ml < 64; ml++) {
            float vv = vb[((size_t)((mc << 6) + ml))*(LV*HW)];
            ull vp = pack2(vv, vv);
            const ull* ap = (const ull*)&As2[ml*132 + c0];
#pragma unroll
            for (int jj = 0; jj < 16; jj++)
                ffma2(acc2[jj], ap[jj], vp);
        }
    }
    float* ob = out + (((size_t)b*COUT + c0)*(NH*DV) + n*DV + d)*HW + hw;
#pragma unroll
    for (int jj = 0; jj < 16; jj++) {
        float2 a = unpack2(acc2[jj]);
        ob[(size_t)(2*jj)    *(NH*DV*HW)] = a.x;
        ob[(size_t)(2*jj + 1)*(NH*DV*HW)] = a.y;
    }
}

// ---------------------------------------------------------------------------
extern "C" void kernel_launch(void* const* d_in, const int* in_sizes, int n_in,
                              void* d_out, int out_size)
{
    const float* input  = (const float*)d_in[0];
    const float* memory = (const float*)d_in[1];
    const float* wq = (const float*)d_in[2];
    const float* bq = (const float*)d_in[3];
    const float* wk = (const float*)d_in[4];
    const float* bk = (const float*)d_in[5];
    const float* wv = (const float*)d_in[6];
    const float* bv = (const float*)d_in[7];
    float* out = (float*)d_out;

    uint32_t *pini, *pmemi, *pwqi, *pwki, *pwvi;
    __half *pqh, *pql, *pkh, *pkl;
    float *pv, *plp, *pattn;
    cudaGetSymbolAddress((void**)&pini,  g_ini);
    cudaGetSymbolAddress((void**)&pmemi, g_memi);
    cudaGetSymbolAddress((void**)&pwqi,  g_wqi);
    cudaGetSymbolAddress((void**)&pwki,  g_wki);
    cudaGetSymbolAddress((void**)&pwvi,  g_wvi);
    cudaGetSymbolAddress((void**)&pqh,   g_qh);
    cudaGetSymbolAddress((void**)&pql,   g_ql);
    cudaGetSymbolAddress((void**)&pkh,   g_kh);
    cudaGetSymbolAddress((void**)&pkl,   g_kl);
    cudaGetSymbolAddress((void**)&pv,    g_v);
    cudaGetSymbolAddress((void**)&plp,   g_lp);
    cudaGetSymbolAddress((void**)&pattn, g_attn);

    const int n4 = (B_*CIN*L_*HW) / 4;        // 2359296
    interleave_kernel<<<n4/256, 256>>>((const float4*)input,  (uint4*)pini,  n4);
    interleave_kernel<<<n4/256, 256>>>((const float4*)memory, (uint4*)pmemi, n4);
    wreorder_kernel<<<COUT, 256>>>(wq, pwqi, 9);
    wreorder_kernel<<<COUT, 256>>>(wk, pwki, 9);
    wreorder_kernel<<<COUT, 256>>>(wv, pwvi, 27);

    conv_mma_kernel<9, L_, 3, true>  <<<dim3(8, L_, B_), 256>>>(
        pini,  pwqi, bq, nullptr, pqh, pql, 0.5f);
    conv_mma_kernel<9, L_, 3, true>  <<<dim3(8, L_, B_), 256>>>(
        pmemi, pwki, bk, nullptr, pkh, pkl, 1.0f);
    conv_mma_kernel<27, LV, 2, false><<<dim3(8, LV, B_), 256>>>(
        pmemi, pwvi, bv, pv, nullptr, nullptr, 1.0f);

    logit_mma_kernel<<<KSPL*B_*NH*DQ, 256>>>(pqh, pql, pkh, pkl, plp);
    softmax_kernel  <<<B_*NH*COUT, 128>>>(plp, pattn);
    out_kernel      <<<dim3(128, B_*NH), 256>>>(pattn, pv, out);
}